// round 4
// baseline (speedup 1.0000x reference)
#include <cuda_runtime.h>
#include <cstdint>

// Problem constants
#define BATCH 16
#define SEQ   2048
#define DMODEL 64
#define HEAD  1024
#define QKVW  3072   // 3*HEAD
#define NTILE 16     // SEQ / 128

// GEMM tile config
#define BM 128
#define BN 128
#define BK 8

// Scratch (device globals; no allocations allowed)
__device__ float g_qkv[(size_t)BATCH * SEQ * QKVW];   // [B*S, 3072]: q|k|v
__device__ float g_p[(size_t)BATCH * SEQ * SEQ];      // [B, S, S] logits -> weights

// ---------------------------------------------------------------------------
// K1: QKV projection.  C[B*S,3072] = X[B*S,64] @ W[64,3072]
// grid (24 n-tiles, 256 m-tiles), 256 threads
// ---------------------------------------------------------------------------
__global__ __launch_bounds__(256)
void qkv_kernel(const float* __restrict__ X, const float* __restrict__ W)
{
    __shared__ float As[BK][BM];
    __shared__ float Bs[BK][BN];

    const int m0 = blockIdx.y * BM;
    const int n0 = blockIdx.x * BN;
    const int t  = threadIdx.x;
    const int tx = t & 15;          // 0..15 (cols)
    const int ty = t >> 4;          // 0..15 (rows)

    // A loader (k-contiguous, transpose into As[k][row])
    const int arow = t >> 1;        // 0..127
    const int acol = (t & 1) * 4;   // 0 or 4
    // B loader (n-contiguous, direct into Bs[k][col])
    const int bk = t >> 5;          // 0..7
    const int bn = (t & 31) * 4;    // 0..124

    float acc[8][8];
    #pragma unroll
    for (int i = 0; i < 8; i++)
        #pragma unroll
        for (int j = 0; j < 8; j++) acc[i][j] = 0.0f;

    for (int k0 = 0; k0 < DMODEL; k0 += BK) {
        float4 av = *(const float4*)&X[(size_t)(m0 + arow) * DMODEL + k0 + acol];
        As[acol + 0][arow] = av.x; As[acol + 1][arow] = av.y;
        As[acol + 2][arow] = av.z; As[acol + 3][arow] = av.w;
        *(float4*)&Bs[bk][bn] = *(const float4*)&W[(size_t)(k0 + bk) * QKVW + n0 + bn];
        __syncthreads();
        #pragma unroll
        for (int kc = 0; kc < BK; ++kc) {
            float4 a0 = *(const float4*)&As[kc][ty * 4];
            float4 a1 = *(const float4*)&As[kc][64 + ty * 4];
            float4 b0 = *(const float4*)&Bs[kc][tx * 4];
            float4 b1 = *(const float4*)&Bs[kc][64 + tx * 4];
            float a[8] = {a0.x, a0.y, a0.z, a0.w, a1.x, a1.y, a1.z, a1.w};
            float b[8] = {b0.x, b0.y, b0.z, b0.w, b1.x, b1.y, b1.z, b1.w};
            #pragma unroll
            for (int i = 0; i < 8; i++)
                #pragma unroll
                for (int j = 0; j < 8; j++)
                    acc[i][j] += a[i] * b[j];
        }
        __syncthreads();
    }

    #pragma unroll
    for (int i = 0; i < 8; i++) {
        int row = m0 + ((i < 4) ? (ty * 4 + i) : (64 + ty * 4 + (i - 4)));
        *(float4*)&g_qkv[(size_t)row * QKVW + n0 + tx * 4] =
            make_float4(acc[i][0], acc[i][1], acc[i][2], acc[i][3]);
        *(float4*)&g_qkv[(size_t)row * QKVW + n0 + 64 + tx * 4] =
            make_float4(acc[i][4], acc[i][5], acc[i][6], acc[i][7]);
    }
}

// ---------------------------------------------------------------------------
// K2: scores.  For upper-triangular tile pairs only:
//   P[b, i, j] = 0.25 * sum_k q[b,i,k]*k[b,j,k]
// grid (136 tile-pairs, 16 batches), 256 threads
// ---------------------------------------------------------------------------
__global__ __launch_bounds__(256)
void qk_kernel()
{
    __shared__ float As[BK][BM];
    __shared__ float Bs[BK][BN];

    // map blockIdx.x -> upper triangular (ti, tj)
    int p = blockIdx.x, ti = 0;
    while (p >= NTILE - ti) { p -= NTILE - ti; ti++; }
    const int tj = ti + p;
    const int b = blockIdx.y;

    const float* Q  = g_qkv + (size_t)b * SEQ * QKVW;          // q at offset 0
    const float* Kp = Q + HEAD;                                 // k at offset 1024
    float* C = g_p + (size_t)b * SEQ * SEQ;

    const int m0 = ti * BM;
    const int n0 = tj * BN;
    const int t  = threadIdx.x;
    const int tx = t & 15;
    const int ty = t >> 4;

    const int arow = t >> 1;
    const int acol = (t & 1) * 4;

    float acc[8][8];
    #pragma unroll
    for (int i = 0; i < 8; i++)
        #pragma unroll
        for (int j = 0; j < 8; j++) acc[i][j] = 0.0f;

    for (int k0 = 0; k0 < HEAD; k0 += BK) {
        float4 av = *(const float4*)&Q[(size_t)(m0 + arow) * QKVW + k0 + acol];
        As[acol + 0][arow] = av.x; As[acol + 1][arow] = av.y;
        As[acol + 2][arow] = av.z; As[acol + 3][arow] = av.w;
        float4 bv = *(const float4*)&Kp[(size_t)(n0 + arow) * QKVW + k0 + acol];
        Bs[acol + 0][arow] = bv.x; Bs[acol + 1][arow] = bv.y;
        Bs[acol + 2][arow] = bv.z; Bs[acol + 3][arow] = bv.w;
        __syncthreads();
        #pragma unroll
        for (int kc = 0; kc < BK; ++kc) {
            float4 a0 = *(const float4*)&As[kc][ty * 4];
            float4 a1 = *(const float4*)&As[kc][64 + ty * 4];
            float4 b0 = *(const float4*)&Bs[kc][tx * 4];
            float4 b1 = *(const float4*)&Bs[kc][64 + tx * 4];
            float a[8] = {a0.x, a0.y, a0.z, a0.w, a1.x, a1.y, a1.z, a1.w};
            float bb[8] = {b0.x, b0.y, b0.z, b0.w, b1.x, b1.y, b1.z, b1.w};
            #pragma unroll
            for (int i = 0; i < 8; i++)
                #pragma unroll
                for (int j = 0; j < 8; j++)
                    acc[i][j] += a[i] * bb[j];
        }
        __syncthreads();
    }

    // store scaled logits (softmax kernel applies all masking)
    #pragma unroll
    for (int i = 0; i < 8; i++) {
        int row = m0 + ((i < 4) ? (ty * 4 + i) : (64 + ty * 4 + (i - 4)));
        *(float4*)&C[(size_t)row * SEQ + n0 + tx * 4] =
            make_float4(acc[i][0] * 0.25f, acc[i][1] * 0.25f,
                        acc[i][2] * 0.25f, acc[i][3] * 0.25f);
        *(float4*)&C[(size_t)row * SEQ + n0 + 64 + tx * 4] =
            make_float4(acc[i][4] * 0.25f, acc[i][5] * 0.25f,
                        acc[i][6] * 0.25f, acc[i][7] * 0.25f);
    }
}

// ---------------------------------------------------------------------------
// K3: row softmax with reference-faithful masking:
//   l_eff[j] = (j >= i && l[j] != 0) ? l[j] : -9e15 ; softmax over all 2048
// grid (B*S rows), 256 threads; full row held in registers
// ---------------------------------------------------------------------------
__global__ __launch_bounds__(256)
void softmax_kernel()
{
    const size_t row = blockIdx.x;        // b*2048 + i
    const int i = (int)(row & (SEQ - 1));
    float* r = g_p + row * SEQ;
    const int t = threadIdx.x;

    float4 v0 = *(const float4*)&r[t * 4];
    float4 v1 = *(const float4*)&r[1024 + t * 4];
    float l[8] = {v0.x, v0.y, v0.z, v0.w, v1.x, v1.y, v1.z, v1.w};

    float m = -3.0e38f;
    #pragma unroll
    for (int e = 0; e < 8; e++) {
        int j = (e < 4) ? (t * 4 + e) : (1024 + t * 4 + (e - 4));
        l[e] = (j >= i && l[e] != 0.0f) ? l[e] : -9.0e15f;
        m = fmaxf(m, l[e]);
    }

    __shared__ float smax[8];
    __shared__ float ssum[8];

    // block max
    #pragma unroll
    for (int o = 16; o; o >>= 1) m = fmaxf(m, __shfl_xor_sync(0xffffffffu, m, o));
    if ((t & 31) == 0) smax[t >> 5] = m;
    __syncthreads();
    if (t == 0) {
        float x = smax[0];
        #pragma unroll
        for (int w = 1; w < 8; w++) x = fmaxf(x, smax[w]);
        smax[0] = x;
    }
    __syncthreads();
    const float bm = smax[0];

    // exp + block sum
    float s = 0.0f;
    float pbuf[8];
    #pragma unroll
    for (int e = 0; e < 8; e++) {
        pbuf[e] = __expf(l[e] - bm);
        s += pbuf[e];
    }
    #pragma unroll
    for (int o = 16; o; o >>= 1) s += __shfl_xor_sync(0xffffffffu, s, o);
    if ((t & 31) == 0) ssum[t >> 5] = s;
    __syncthreads();
    if (t == 0) {
        float x = ssum[0];
        #pragma unroll
        for (int w = 1; w < 8; w++) x += ssum[w];
        ssum[0] = x;
    }
    __syncthreads();
    const float inv = 1.0f / ssum[0];

    *(float4*)&r[t * 4] =
        make_float4(pbuf[0] * inv, pbuf[1] * inv, pbuf[2] * inv, pbuf[3] * inv);
    *(float4*)&r[1024 + t * 4] =
        make_float4(pbuf[4] * inv, pbuf[5] * inv, pbuf[6] * inv, pbuf[7] * inv);
}

// ---------------------------------------------------------------------------
// K4: out = P @ V, skipping all-zero k-blocks (k starts at row tile)
// grid (8 n-tiles, 16 row tiles, 16 batches), 256 threads
// ---------------------------------------------------------------------------
__global__ __launch_bounds__(256)
void pv_kernel(float* __restrict__ Out)
{
    __shared__ float As[BK][BM];
    __shared__ float Bs[BK][BN];

    const int b  = blockIdx.z;
    const int ti = blockIdx.y;
    const int n0 = blockIdx.x * BN;

    const float* A = g_p + (size_t)b * SEQ * SEQ;                 // lda = SEQ
    const float* V = g_qkv + (size_t)b * SEQ * QKVW + 2 * HEAD;   // ldb = QKVW
    float* C = Out + (size_t)b * SEQ * HEAD;

    const int m0 = ti * BM;
    const int t  = threadIdx.x;
    const int tx = t & 15;
    const int ty = t >> 4;

    const int arow = t >> 1;
    const int acol = (t & 1) * 4;
    const int bk = t >> 5;
    const int bn = (t & 31) * 4;

    float acc[8][8];
    #pragma unroll
    for (int i = 0; i < 8; i++)
        #pragma unroll
        for (int j = 0; j < 8; j++) acc[i][j] = 0.0f;

    for (int k0 = m0; k0 < SEQ; k0 += BK) {
        float4 av = *(const float4*)&A[(size_t)(m0 + arow) * SEQ + k0 + acol];
        As[acol + 0][arow] = av.x; As[acol + 1][arow] = av.y;
        As[acol + 2][arow] = av.z; As[acol + 3][arow] = av.w;
        *(float4*)&Bs[bk][bn] = *(const float4*)&V[(size_t)(k0 + bk) * QKVW + n0 + bn];
        __syncthreads();
        #pragma unroll
        for (int kc = 0; kc < BK; ++kc) {
            float4 a0 = *(const float4*)&As[kc][ty * 4];
            float4 a1 = *(const float4*)&As[kc][64 + ty * 4];
            float4 b0 = *(const float4*)&Bs[kc][tx * 4];
            float4 b1 = *(const float4*)&Bs[kc][64 + tx * 4];
            float a[8] = {a0.x, a0.y, a0.z, a0.w, a1.x, a1.y, a1.z, a1.w};
            float bb[8] = {b0.x, b0.y, b0.z, b0.w, b1.x, b1.y, b1.z, b1.w};
            #pragma unroll
            for (int i = 0; i < 8; i++)
                #pragma unroll
                for (int j = 0; j < 8; j++)
                    acc[i][j] += a[i] * bb[j];
        }
        __syncthreads();
    }

    #pragma unroll
    for (int i = 0; i < 8; i++) {
        int row = m0 + ((i < 4) ? (ty * 4 + i) : (64 + ty * 4 + (i - 4)));
        *(float4*)&C[(size_t)row * HEAD + n0 + tx * 4] =
            make_float4(acc[i][0], acc[i][1], acc[i][2], acc[i][3]);
        *(float4*)&C[(size_t)row * HEAD + n0 + 64 + tx * 4] =
            make_float4(acc[i][4], acc[i][5], acc[i][6], acc[i][7]);
    }
}

// ---------------------------------------------------------------------------
extern "C" void kernel_launch(void* const* d_in, const int* in_sizes, int n_in,
                              void* d_out, int out_size)
{
    (void)in_sizes; (void)n_in; (void)out_size;
    const float* x = (const float*)d_in[0];   // [16, 2048, 64]
    const float* W = (const float*)d_in[1];   // [64, 3072]
    float* out = (float*)d_out;               // [16, 2048, 1024]

    qkv_kernel<<<dim3(QKVW / BN, (BATCH * SEQ) / BM), 256>>>(x, W);
    qk_kernel<<<dim3(NTILE * (NTILE + 1) / 2, BATCH), 256>>>();
    softmax_kernel<<<dim3(BATCH * SEQ), 256>>>();
    pv_kernel<<<dim3(HEAD / BN, NTILE, BATCH), 256>>>(out);
}

// round 12
// speedup vs baseline: 1.7769x; 1.7769x over previous
#include <cuda_runtime.h>
#include <cuda_bf16.h>
#include <cstdint>

// Problem constants
#define BATCH 16
#define SEQ   2048
#define DMODEL 64
#define HEAD  1024
#define QKVW  3072
#define NTILE 16      // SEQ/128

// Padded smem tile geometry (bf16): 128 rows x 64 cols, stride 72 (conflict-free LDSM)
#define TSTRIDE 72
#define TILE_ELEMS (128 * TSTRIDE)   // 9216 bf16 per tile
#define SMEM_BYTES (4 * TILE_ELEMS * 2)  // Ah, Al, Bh, Bl = 73728 B

// ---------------------------------------------------------------------------
// Scratch (device globals; allocations are forbidden)
// ---------------------------------------------------------------------------
__device__ __align__(16) __nv_bfloat16 g_q_hi[(size_t)BATCH * SEQ * HEAD];
__device__ __align__(16) __nv_bfloat16 g_q_lo[(size_t)BATCH * SEQ * HEAD];
__device__ __align__(16) __nv_bfloat16 g_k_hi[(size_t)BATCH * SEQ * HEAD];
__device__ __align__(16) __nv_bfloat16 g_k_lo[(size_t)BATCH * SEQ * HEAD];
__device__ __align__(16) float         g_v   [(size_t)BATCH * SEQ * HEAD];
__device__ __align__(16) __nv_bfloat16 g_vt_hi[(size_t)BATCH * HEAD * SEQ];
__device__ __align__(16) __nv_bfloat16 g_vt_lo[(size_t)BATCH * HEAD * SEQ];
__device__ __align__(16) float         g_p   [(size_t)BATCH * SEQ * SEQ];
__device__ __align__(16) __nv_bfloat16 g_p_hi[(size_t)BATCH * SEQ * SEQ];
__device__ __align__(16) __nv_bfloat16 g_p_lo[(size_t)BATCH * SEQ * SEQ];

// ---------------------------------------------------------------------------
// Warp-MMA primitives (sm_80-compatible PTX; works under compute_103 target)
// ---------------------------------------------------------------------------
__device__ __forceinline__ uint32_t smem_u32(const void* p) {
    uint32_t a;
    asm("{ .reg .u64 t; cvta.to.shared.u64 t, %1; cvt.u32.u64 %0, t; }"
        : "=r"(a) : "l"(p));
    return a;
}
__device__ __forceinline__ void ldm4(uint32_t* r, uint32_t a) {
    asm volatile("ldmatrix.sync.aligned.m8n8.x4.shared.b16 {%0,%1,%2,%3}, [%4];"
                 : "=r"(r[0]), "=r"(r[1]), "=r"(r[2]), "=r"(r[3]) : "r"(a));
}
__device__ __forceinline__ void ldm2(uint32_t* r, uint32_t a) {
    asm volatile("ldmatrix.sync.aligned.m8n8.x2.shared.b16 {%0,%1}, [%2];"
                 : "=r"(r[0]), "=r"(r[1]) : "r"(a));
}
__device__ __forceinline__ void mma16816(float* c, const uint32_t* a, const uint32_t* b) {
    asm volatile(
        "mma.sync.aligned.m16n8k16.row.col.f32.bf16.bf16.f32 "
        "{%0,%1,%2,%3}, {%4,%5,%6,%7}, {%8,%9}, {%0,%1,%2,%3};"
        : "+f"(c[0]), "+f"(c[1]), "+f"(c[2]), "+f"(c[3])
        : "r"(a[0]), "r"(a[1]), "r"(a[2]), "r"(a[3]), "r"(b[0]), "r"(b[1]));
}

// bf16 split helpers
__device__ __forceinline__ void split_bf16(float x, __nv_bfloat16& h, __nv_bfloat16& l) {
    h = __float2bfloat16_rn(x);
    l = __float2bfloat16_rn(x - __bfloat162float(h));
}

// ---------------------------------------------------------------------------
// K1: QKV projection (fp32 SIMT), epilogue emits q/k hi+lo bf16 and v fp32
// ---------------------------------------------------------------------------
__global__ __launch_bounds__(256)
void qkv_kernel(const float* __restrict__ X, const float* __restrict__ W)
{
    __shared__ float As[8][128];
    __shared__ float Bs[8][128];

    const int m0 = blockIdx.y * 128;
    const int n0 = blockIdx.x * 128;
    const int t  = threadIdx.x;
    const int tx = t & 15, ty = t >> 4;
    const int arow = t >> 1, acol = (t & 1) * 4;
    const int bk = t >> 5,  bn = (t & 31) * 4;

    float acc[8][8];
    #pragma unroll
    for (int i = 0; i < 8; i++)
        #pragma unroll
        for (int j = 0; j < 8; j++) acc[i][j] = 0.0f;

    for (int k0 = 0; k0 < DMODEL; k0 += 8) {
        float4 av = *(const float4*)&X[(size_t)(m0 + arow) * DMODEL + k0 + acol];
        As[acol + 0][arow] = av.x; As[acol + 1][arow] = av.y;
        As[acol + 2][arow] = av.z; As[acol + 3][arow] = av.w;
        *(float4*)&Bs[bk][bn] = *(const float4*)&W[(size_t)(k0 + bk) * QKVW + n0 + bn];
        __syncthreads();
        #pragma unroll
        for (int kc = 0; kc < 8; ++kc) {
            float4 a0 = *(const float4*)&As[kc][ty * 4];
            float4 a1 = *(const float4*)&As[kc][64 + ty * 4];
            float4 b0 = *(const float4*)&Bs[kc][tx * 4];
            float4 b1 = *(const float4*)&Bs[kc][64 + tx * 4];
            float a[8] = {a0.x, a0.y, a0.z, a0.w, a1.x, a1.y, a1.z, a1.w};
            float b[8] = {b0.x, b0.y, b0.z, b0.w, b1.x, b1.y, b1.z, b1.w};
            #pragma unroll
            for (int i = 0; i < 8; i++)
                #pragma unroll
                for (int j = 0; j < 8; j++)
                    acc[i][j] += a[i] * b[j];
        }
        __syncthreads();
    }

    const int sec = n0 >> 10;              // 0=q, 1=k, 2=v
    const int cb  = n0 & 1023;

    #pragma unroll
    for (int i = 0; i < 8; i++) {
        int row = m0 + ((i < 4) ? (ty * 4 + i) : (64 + ty * 4 + (i - 4)));
        #pragma unroll
        for (int h = 0; h < 2; h++) {
            int col = cb + h * 64 + tx * 4;
            float v0 = acc[i][h * 4 + 0], v1 = acc[i][h * 4 + 1];
            float v2 = acc[i][h * 4 + 2], v3 = acc[i][h * 4 + 3];
            if (sec == 2) {
                *(float4*)&g_v[(size_t)row * HEAD + col] = make_float4(v0, v1, v2, v3);
            } else {
                __nv_bfloat16 h0, l0, h1, l1, h2, l2, h3, l3;
                split_bf16(v0, h0, l0); split_bf16(v1, h1, l1);
                split_bf16(v2, h2, l2); split_bf16(v3, h3, l3);
                __nv_bfloat16* hp = sec == 0 ? g_q_hi : g_k_hi;
                __nv_bfloat16* lp = sec == 0 ? g_q_lo : g_k_lo;
                ushort4 hs, ls;
                hs.x = __bfloat16_as_ushort(h0); hs.y = __bfloat16_as_ushort(h1);
                hs.z = __bfloat16_as_ushort(h2); hs.w = __bfloat16_as_ushort(h3);
                ls.x = __bfloat16_as_ushort(l0); ls.y = __bfloat16_as_ushort(l1);
                ls.z = __bfloat16_as_ushort(l2); ls.w = __bfloat16_as_ushort(l3);
                *(ushort4*)&hp[(size_t)row * HEAD + col] = hs;
                *(ushort4*)&lp[(size_t)row * HEAD + col] = ls;
            }
        }
    }
}

// ---------------------------------------------------------------------------
// K2: transpose v (fp32) -> vt hi/lo (bf16), per-batch [HEAD][SEQ]
// ---------------------------------------------------------------------------
__global__ __launch_bounds__(256)
void vt_kernel()
{
    __shared__ float tile[64][65];
    const int b  = blockIdx.z;
    const int s0 = blockIdx.y * 64;
    const int n0 = blockIdx.x * 64;
    const float* V = g_v + (size_t)b * SEQ * HEAD;
    const int t = threadIdx.x;

    #pragma unroll
    for (int i = 0; i < 16; i++) {
        int idx = t + i * 256;
        int r = idx >> 6, c = idx & 63;
        tile[r][c] = V[(size_t)(s0 + r) * HEAD + n0 + c];
    }
    __syncthreads();
    #pragma unroll
    for (int i = 0; i < 16; i++) {
        int idx = t + i * 256;
        int r = idx >> 6, c = idx & 63;       // r = local n, c = local s
        float x = tile[c][r];
        __nv_bfloat16 h, l;
        split_bf16(x, h, l);
        size_t o = ((size_t)b * HEAD + n0 + r) * SEQ + s0 + c;
        g_vt_hi[o] = h;
        g_vt_lo[o] = l;
    }
}

// ---------------------------------------------------------------------------
// Shared tile loader: 4 tiles of [128 rows x 64 bf16] into padded smem
// ---------------------------------------------------------------------------
template <int STRIDE>
__device__ __forceinline__ void load_tiles(__nv_bfloat16* tp,
    const __nv_bfloat16* s0, const __nv_bfloat16* s1,
    const __nv_bfloat16* s2, const __nv_bfloat16* s3, int k0, int t)
{
    const __nv_bfloat16* srcs[4] = {s0, s1, s2, s3};
    #pragma unroll
    for (int tl = 0; tl < 4; ++tl) {
        #pragma unroll
        for (int it = 0; it < 4; ++it) {
            int idx = t + it * 256;               // 0..1023
            int r = idx >> 3, c = idx & 7;
            float4 v = *(const float4*)(srcs[tl] + (size_t)r * STRIDE + k0 + c * 8);
            *(float4*)(tp + tl * TILE_ELEMS + r * TSTRIDE + c * 8) = v;
        }
    }
}

// ---------------------------------------------------------------------------
// Warp-MMA mainloop over one staged 64-chunk: 3 split passes (hh, lh, hl)
// acc[4][4][4]; warp tile 64x32 at (wm, wn) inside the 128x128 CTA tile
// ---------------------------------------------------------------------------
__device__ __forceinline__ void mma_chunk_warp(
    float acc[4][4][4],
    uint32_t aBaseH, uint32_t aBaseL, uint32_t bBaseH, uint32_t bBaseL)
{
    #pragma unroll
    for (int ks = 0; ks < 4; ++ks) {
        uint32_t bh[4][2], bl[4][2];
        #pragma unroll
        for (int nt = 0; nt < 4; ++nt) {
            ldm2(bh[nt], bBaseH + nt * (8 * TSTRIDE * 2) + ks * 32);
            ldm2(bl[nt], bBaseL + nt * (8 * TSTRIDE * 2) + ks * 32);
        }
        #pragma unroll
        for (int mt = 0; mt < 4; ++mt) {
            uint32_t ah[4], al[4];
            ldm4(ah, aBaseH + mt * (16 * TSTRIDE * 2) + ks * 32);
            ldm4(al, aBaseL + mt * (16 * TSTRIDE * 2) + ks * 32);
            #pragma unroll
            for (int nt = 0; nt < 4; ++nt) {
                mma16816(acc[mt][nt], ah, bh[nt]);
                mma16816(acc[mt][nt], al, bh[nt]);
                mma16816(acc[mt][nt], ah, bl[nt]);
            }
        }
    }
}

// Per-thread ldmatrix base addresses inside the staged tiles
__device__ __forceinline__ void frag_bases(
    uint32_t sbase, int wm, int wn, int lane,
    uint32_t& aBaseH, uint32_t& aBaseL, uint32_t& bBaseH, uint32_t& bBaseL)
{
    const int lr = lane & 7;
    const int sel = lane >> 3;                   // 0..3
    // A x4: mats = (m0-7,k0-7),(m8-15,k0-7),(m0-7,k8-15),(m8-15,k8-15)
    const int aRow = wm + (sel & 1) * 8 + lr;
    const int aK   = (sel >> 1) * 8;
    aBaseH = sbase + 2u * (0 * TILE_ELEMS + aRow * TSTRIDE + aK);
    aBaseL = sbase + 2u * (1 * TILE_ELEMS + aRow * TSTRIDE + aK);
    // B x2: mats = (n0-7,k0-7),(n0-7,k8-15); lanes 16-31 unused but valid
    const int bRow = wn + lr;
    const int bK   = (sel & 1) * 8;
    bBaseH = sbase + 2u * (2 * TILE_ELEMS + bRow * TSTRIDE + bK);
    bBaseL = sbase + 2u * (3 * TILE_ELEMS + bRow * TSTRIDE + bK);
}

// ---------------------------------------------------------------------------
// K3: QK^T upper-triangular tiles via warp HMMA (split bf16, 3 passes)
// ---------------------------------------------------------------------------
__global__ __launch_bounds__(256)
void qk_mma_kernel()
{
    extern __shared__ __nv_bfloat16 smem[];
    const uint32_t sbase = smem_u32(smem);
    const int t = threadIdx.x;
    const int lane = t & 31, wid = t >> 5;
    const int wm = (wid >> 2) * 64;     // warp m offset (0 or 64)
    const int wn = (wid & 3) * 32;      // warp n offset (0,32,64,96)

    int p = blockIdx.x, ti = 0;
    while (p >= NTILE - ti) { p -= NTILE - ti; ti++; }
    const int tj = ti + p;
    const int b  = blockIdx.y;
    const int m0 = ti * 128, n0 = tj * 128;

    const __nv_bfloat16* Ah = g_q_hi + ((size_t)b * SEQ + m0) * HEAD;
    const __nv_bfloat16* Al = g_q_lo + ((size_t)b * SEQ + m0) * HEAD;
    const __nv_bfloat16* Bh = g_k_hi + ((size_t)b * SEQ + n0) * HEAD;
    const __nv_bfloat16* Bl = g_k_lo + ((size_t)b * SEQ + n0) * HEAD;

    uint32_t aBH, aBL, bBH, bBL;
    frag_bases(sbase, wm, wn, lane, aBH, aBL, bBH, bBL);

    float acc[4][4][4];
    #pragma unroll
    for (int i = 0; i < 4; i++)
        #pragma unroll
        for (int j = 0; j < 4; j++)
            #pragma unroll
            for (int r = 0; r < 4; r++) acc[i][j][r] = 0.0f;

    for (int c = 0; c < HEAD / 64; ++c) {
        load_tiles<HEAD>(smem, Ah, Al, Bh, Bl, c * 64, t);
        __syncthreads();
        mma_chunk_warp(acc, aBH, aBL, bBH, bBL);
        __syncthreads();
    }

    // epilogue: scaled logits to g_p
    float* C = g_p + (size_t)b * SEQ * SEQ;
    const int row0 = m0 + wm + (lane >> 2);
    const int col0 = n0 + wn + (lane & 3) * 2;
    #pragma unroll
    for (int mt = 0; mt < 4; ++mt)
        #pragma unroll
        for (int nt = 0; nt < 4; ++nt) {
            int r1 = row0 + mt * 16, c1 = col0 + nt * 8;
            *(float2*)&C[(size_t)r1 * SEQ + c1] =
                make_float2(acc[mt][nt][0] * 0.25f, acc[mt][nt][1] * 0.25f);
            *(float2*)&C[(size_t)(r1 + 8) * SEQ + c1] =
                make_float2(acc[mt][nt][2] * 0.25f, acc[mt][nt][3] * 0.25f);
        }
}

// ---------------------------------------------------------------------------
// K4: row softmax (reference-faithful masking), writes P hi/lo bf16
// ---------------------------------------------------------------------------
__global__ __launch_bounds__(256)
void softmax_kernel()
{
    const size_t row = blockIdx.x;
    const int i = (int)(row & (SEQ - 1));
    const float* r = g_p + row * SEQ;
    __nv_bfloat16* ph = g_p_hi + row * SEQ;
    __nv_bfloat16* pl = g_p_lo + row * SEQ;
    const int t = threadIdx.x;

    float4 v0 = *(const float4*)&r[t * 4];
    float4 v1 = *(const float4*)&r[1024 + t * 4];
    float l[8] = {v0.x, v0.y, v0.z, v0.w, v1.x, v1.y, v1.z, v1.w};

    float m = -3.0e38f;
    #pragma unroll
    for (int e = 0; e < 8; e++) {
        int j = (e < 4) ? (t * 4 + e) : (1024 + t * 4 + (e - 4));
        l[e] = (j >= i && l[e] != 0.0f) ? l[e] : -9.0e15f;
        m = fmaxf(m, l[e]);
    }

    __shared__ float smax[8];
    __shared__ float ssum[8];

    #pragma unroll
    for (int o = 16; o; o >>= 1) m = fmaxf(m, __shfl_xor_sync(0xffffffffu, m, o));
    if ((t & 31) == 0) smax[t >> 5] = m;
    __syncthreads();
    if (t == 0) {
        float x = smax[0];
        #pragma unroll
        for (int w = 1; w < 8; w++) x = fmaxf(x, smax[w]);
        smax[0] = x;
    }
    __syncthreads();
    const float bm = smax[0];

    float s = 0.0f;
    float pb[8];
    #pragma unroll
    for (int e = 0; e < 8; e++) { pb[e] = __expf(l[e] - bm); s += pb[e]; }
    #pragma unroll
    for (int o = 16; o; o >>= 1) s += __shfl_xor_sync(0xffffffffu, s, o);
    if ((t & 31) == 0) ssum[t >> 5] = s;
    __syncthreads();
    if (t == 0) {
        float x = ssum[0];
        #pragma unroll
        for (int w = 1; w < 8; w++) x += ssum[w];
        ssum[0] = x;
    }
    __syncthreads();
    const float inv = 1.0f / ssum[0];

    #pragma unroll
    for (int h = 0; h < 2; h++) {
        int col = h * 1024 + t * 4;
        __nv_bfloat16 h0, l0, h1, l1, h2, l2, h3, l3;
        split_bf16(pb[h * 4 + 0] * inv, h0, l0);
        split_bf16(pb[h * 4 + 1] * inv, h1, l1);
        split_bf16(pb[h * 4 + 2] * inv, h2, l2);
        split_bf16(pb[h * 4 + 3] * inv, h3, l3);
        ushort4 hs, ls;
        hs.x = __bfloat16_as_ushort(h0); hs.y = __bfloat16_as_ushort(h1);
        hs.z = __bfloat16_as_ushort(h2); hs.w = __bfloat16_as_ushort(h3);
        ls.x = __bfloat16_as_ushort(l0); ls.y = __bfloat16_as_ushort(l1);
        ls.z = __bfloat16_as_ushort(l2); ls.w = __bfloat16_as_ushort(l3);
        *(ushort4*)&ph[col] = hs;
        *(ushort4*)&pl[col] = ls;
    }
}

// ---------------------------------------------------------------------------
// K5: out = P @ V via warp HMMA (split bf16, 3 passes), triangular K skip
// ---------------------------------------------------------------------------
__global__ __launch_bounds__(256)
void pv_mma_kernel(float* __restrict__ Out)
{
    extern __shared__ __nv_bfloat16 smem[];
    const uint32_t sbase = smem_u32(smem);
    const int t = threadIdx.x;
    const int lane = t & 31, wid = t >> 5;
    const int wm = (wid >> 2) * 64;
    const int wn = (wid & 3) * 32;

    const int b  = blockIdx.z;
    const int ti = blockIdx.y;
    const int n0 = blockIdx.x * 128;
    const int m0 = ti * 128;

    const __nv_bfloat16* Ah = g_p_hi  + ((size_t)b * SEQ + m0) * SEQ;
    const __nv_bfloat16* Al = g_p_lo  + ((size_t)b * SEQ + m0) * SEQ;
    const __nv_bfloat16* Bh = g_vt_hi + ((size_t)b * HEAD + n0) * SEQ;
    const __nv_bfloat16* Bl = g_vt_lo + ((size_t)b * HEAD + n0) * SEQ;

    uint32_t aBH, aBL, bBH, bBL;
    frag_bases(sbase, wm, wn, lane, aBH, aBL, bBH, bBL);

    float acc[4][4][4];
    #pragma unroll
    for (int i = 0; i < 4; i++)
        #pragma unroll
        for (int j = 0; j < 4; j++)
            #pragma unroll
            for (int r = 0; r < 4; r++) acc[i][j][r] = 0.0f;

    const int nchunks = (SEQ - m0) / 64;
    for (int c = 0; c < nchunks; ++c) {
        load_tiles<SEQ>(smem, Ah, Al, Bh, Bl, m0 + c * 64, t);
        __syncthreads();
        mma_chunk_warp(acc, aBH, aBL, bBH, bBL);
        __syncthreads();
    }

    float* C = Out + (size_t)b * SEQ * HEAD;
    const int row0 = m0 + wm + (lane >> 2);
    const int col0 = n0 + wn + (lane & 3) * 2;
    #pragma unroll
    for (int mt = 0; mt < 4; ++mt)
        #pragma unroll
        for (int nt = 0; nt < 4; ++nt) {
            int r1 = row0 + mt * 16, c1 = col0 + nt * 8;
            *(float2*)&C[(size_t)r1 * HEAD + c1] =
                make_float2(acc[mt][nt][0], acc[mt][nt][1]);
            *(float2*)&C[(size_t)(r1 + 8) * HEAD + c1] =
                make_float2(acc[mt][nt][2], acc[mt][nt][3]);
        }
}

// ---------------------------------------------------------------------------
extern "C" void kernel_launch(void* const* d_in, const int* in_sizes, int n_in,
                              void* d_out, int out_size)
{
    (void)in_sizes; (void)n_in; (void)out_size;
    const float* x = (const float*)d_in[0];   // [16, 2048, 64]
    const float* W = (const float*)d_in[1];   // [64, 3072]
    float* out = (float*)d_out;               // [16, 2048, 1024]

    cudaFuncSetAttribute(qk_mma_kernel, cudaFuncAttributeMaxDynamicSharedMemorySize, SMEM_BYTES);
    cudaFuncSetAttribute(pv_mma_kernel, cudaFuncAttributeMaxDynamicSharedMemorySize, SMEM_BYTES);

    qkv_kernel<<<dim3(QKVW / 128, (BATCH * SEQ) / 128), 256>>>(x, W);
    vt_kernel<<<dim3(HEAD / 64, SEQ / 64, BATCH), 256>>>();
    qk_mma_kernel<<<dim3(NTILE * (NTILE + 1) / 2, BATCH), 256, SMEM_BYTES>>>();
    softmax_kernel<<<dim3(BATCH * SEQ), 256>>>();
    pv_mma_kernel<<<dim3(HEAD / 128, NTILE, BATCH), 256, SMEM_BYTES>>>(out);
}

// round 14
// speedup vs baseline: 2.2399x; 1.2606x over previous
#include <cuda_runtime.h>
#include <cuda_bf16.h>
#include <cstdint>

// Problem constants
#define BATCH 16
#define SEQ   2048
#define DMODEL 64
#define HEAD  1024
#define QKVW  3072
#define NTILE 16      // SEQ/128

// Padded smem tile geometry (bf16): 128 rows x 64 cols, stride 72 (conflict-free LDSM)
#define TSTRIDE 72
#define TILE_ELEMS (128 * TSTRIDE)            // 9216 bf16 per tile
#define BUF_ELEMS  (4 * TILE_ELEMS)           // Ah, Al, Bh, Bl
#define BUF_BYTES  (BUF_ELEMS * 2)            // 73728 B
#define SMEM_BYTES (2 * BUF_BYTES)            // double buffered = 147456 B

// ---------------------------------------------------------------------------
// Scratch (device globals; allocations are forbidden)
// ---------------------------------------------------------------------------
__device__ __align__(16) __nv_bfloat16 g_q_hi[(size_t)BATCH * SEQ * HEAD];
__device__ __align__(16) __nv_bfloat16 g_q_lo[(size_t)BATCH * SEQ * HEAD];
__device__ __align__(16) __nv_bfloat16 g_k_hi[(size_t)BATCH * SEQ * HEAD];
__device__ __align__(16) __nv_bfloat16 g_k_lo[(size_t)BATCH * SEQ * HEAD];
__device__ __align__(16) float         g_v   [(size_t)BATCH * SEQ * HEAD];
__device__ __align__(16) __nv_bfloat16 g_vt_hi[(size_t)BATCH * HEAD * SEQ];
__device__ __align__(16) __nv_bfloat16 g_vt_lo[(size_t)BATCH * HEAD * SEQ];
__device__ __align__(16) float         g_p   [(size_t)BATCH * SEQ * SEQ];
__device__ __align__(16) __nv_bfloat16 g_p_hi[(size_t)BATCH * SEQ * SEQ];
__device__ __align__(16) __nv_bfloat16 g_p_lo[(size_t)BATCH * SEQ * SEQ];

// ---------------------------------------------------------------------------
// Warp-MMA + cp.async primitives (sm_80-compatible PTX under compute_103)
// ---------------------------------------------------------------------------
__device__ __forceinline__ uint32_t smem_u32(const void* p) {
    uint32_t a;
    asm("{ .reg .u64 t; cvta.to.shared.u64 t, %1; cvt.u32.u64 %0, t; }"
        : "=r"(a) : "l"(p));
    return a;
}
__device__ __forceinline__ void ldm4(uint32_t* r, uint32_t a) {
    asm volatile("ldmatrix.sync.aligned.m8n8.x4.shared.b16 {%0,%1,%2,%3}, [%4];"
                 : "=r"(r[0]), "=r"(r[1]), "=r"(r[2]), "=r"(r[3]) : "r"(a));
}
__device__ __forceinline__ void ldm2(uint32_t* r, uint32_t a) {
    asm volatile("ldmatrix.sync.aligned.m8n8.x2.shared.b16 {%0,%1}, [%2];"
                 : "=r"(r[0]), "=r"(r[1]) : "r"(a));
}
__device__ __forceinline__ void mma16816(float* c, const uint32_t* a, const uint32_t* b) {
    asm volatile(
        "mma.sync.aligned.m16n8k16.row.col.f32.bf16.bf16.f32 "
        "{%0,%1,%2,%3}, {%4,%5,%6,%7}, {%8,%9}, {%0,%1,%2,%3};"
        : "+f"(c[0]), "+f"(c[1]), "+f"(c[2]), "+f"(c[3])
        : "r"(a[0]), "r"(a[1]), "r"(a[2]), "r"(a[3]), "r"(b[0]), "r"(b[1]));
}
__device__ __forceinline__ void cp16(uint32_t dst, const void* src) {
    asm volatile("cp.async.cg.shared.global [%0], [%1], 16;"
                 :: "r"(dst), "l"(src));
}
#define CP_COMMIT() asm volatile("cp.async.commit_group;" ::: "memory")
template <int N>
__device__ __forceinline__ void cp_wait() {
    asm volatile("cp.async.wait_group %0;" :: "n"(N) : "memory");
}

// bf16 split helpers
__device__ __forceinline__ void split_bf16(float x, __nv_bfloat16& h, __nv_bfloat16& l) {
    h = __float2bfloat16_rn(x);
    l = __float2bfloat16_rn(x - __bfloat162float(h));
}

// ---------------------------------------------------------------------------
// K1: QKV projection (fp32 SIMT), epilogue emits q/k hi+lo bf16 and v fp32
// ---------------------------------------------------------------------------
__global__ __launch_bounds__(256)
void qkv_kernel(const float* __restrict__ X, const float* __restrict__ W)
{
    __shared__ float As[8][128];
    __shared__ float Bs[8][128];

    const int m0 = blockIdx.y * 128;
    const int n0 = blockIdx.x * 128;
    const int t  = threadIdx.x;
    const int tx = t & 15, ty = t >> 4;
    const int arow = t >> 1, acol = (t & 1) * 4;
    const int bk = t >> 5,  bn = (t & 31) * 4;

    float acc[8][8];
    #pragma unroll
    for (int i = 0; i < 8; i++)
        #pragma unroll
        for (int j = 0; j < 8; j++) acc[i][j] = 0.0f;

    for (int k0 = 0; k0 < DMODEL; k0 += 8) {
        float4 av = *(const float4*)&X[(size_t)(m0 + arow) * DMODEL + k0 + acol];
        As[acol + 0][arow] = av.x; As[acol + 1][arow] = av.y;
        As[acol + 2][arow] = av.z; As[acol + 3][arow] = av.w;
        *(float4*)&Bs[bk][bn] = *(const float4*)&W[(size_t)(k0 + bk) * QKVW + n0 + bn];
        __syncthreads();
        #pragma unroll
        for (int kc = 0; kc < 8; ++kc) {
            float4 a0 = *(const float4*)&As[kc][ty * 4];
            float4 a1 = *(const float4*)&As[kc][64 + ty * 4];
            float4 b0 = *(const float4*)&Bs[kc][tx * 4];
            float4 b1 = *(const float4*)&Bs[kc][64 + tx * 4];
            float a[8] = {a0.x, a0.y, a0.z, a0.w, a1.x, a1.y, a1.z, a1.w};
            float b[8] = {b0.x, b0.y, b0.z, b0.w, b1.x, b1.y, b1.z, b1.w};
            #pragma unroll
            for (int i = 0; i < 8; i++)
                #pragma unroll
                for (int j = 0; j < 8; j++)
                    acc[i][j] += a[i] * b[j];
        }
        __syncthreads();
    }

    const int sec = n0 >> 10;              // 0=q, 1=k, 2=v
    const int cb  = n0 & 1023;

    #pragma unroll
    for (int i = 0; i < 8; i++) {
        int row = m0 + ((i < 4) ? (ty * 4 + i) : (64 + ty * 4 + (i - 4)));
        #pragma unroll
        for (int h = 0; h < 2; h++) {
            int col = cb + h * 64 + tx * 4;
            float v0 = acc[i][h * 4 + 0], v1 = acc[i][h * 4 + 1];
            float v2 = acc[i][h * 4 + 2], v3 = acc[i][h * 4 + 3];
            if (sec == 2) {
                *(float4*)&g_v[(size_t)row * HEAD + col] = make_float4(v0, v1, v2, v3);
            } else {
                __nv_bfloat16 h0, l0, h1, l1, h2, l2, h3, l3;
                split_bf16(v0, h0, l0); split_bf16(v1, h1, l1);
                split_bf16(v2, h2, l2); split_bf16(v3, h3, l3);
                __nv_bfloat16* hp = sec == 0 ? g_q_hi : g_k_hi;
                __nv_bfloat16* lp = sec == 0 ? g_q_lo : g_k_lo;
                ushort4 hs, ls;
                hs.x = __bfloat16_as_ushort(h0); hs.y = __bfloat16_as_ushort(h1);
                hs.z = __bfloat16_as_ushort(h2); hs.w = __bfloat16_as_ushort(h3);
                ls.x = __bfloat16_as_ushort(l0); ls.y = __bfloat16_as_ushort(l1);
                ls.z = __bfloat16_as_ushort(l2); ls.w = __bfloat16_as_ushort(l3);
                *(ushort4*)&hp[(size_t)row * HEAD + col] = hs;
                *(ushort4*)&lp[(size_t)row * HEAD + col] = ls;
            }
        }
    }
}

// ---------------------------------------------------------------------------
// K2: transpose v (fp32) -> vt hi/lo (bf16), per-batch [HEAD][SEQ]
// ---------------------------------------------------------------------------
__global__ __launch_bounds__(256)
void vt_kernel()
{
    __shared__ float tile[64][65];
    const int b  = blockIdx.z;
    const int s0 = blockIdx.y * 64;
    const int n0 = blockIdx.x * 64;
    const float* V = g_v + (size_t)b * SEQ * HEAD;
    const int t = threadIdx.x;

    #pragma unroll
    for (int i = 0; i < 16; i++) {
        int idx = t + i * 256;
        int r = idx >> 6, c = idx & 63;
        tile[r][c] = V[(size_t)(s0 + r) * HEAD + n0 + c];
    }
    __syncthreads();
    #pragma unroll
    for (int i = 0; i < 16; i++) {
        int idx = t + i * 256;
        int r = idx >> 6, c = idx & 63;       // r = local n, c = local s
        float x = tile[c][r];
        __nv_bfloat16 h, l;
        split_bf16(x, h, l);
        size_t o = ((size_t)b * HEAD + n0 + r) * SEQ + s0 + c;
        g_vt_hi[o] = h;
        g_vt_lo[o] = l;
    }
}

// ---------------------------------------------------------------------------
// Async tile loader: 4 tiles of [128 rows x 64 bf16] into padded smem buffer
// ---------------------------------------------------------------------------
template <int STRIDE>
__device__ __forceinline__ void load_tiles_async(__nv_bfloat16* tp,
    const __nv_bfloat16* s0, const __nv_bfloat16* s1,
    const __nv_bfloat16* s2, const __nv_bfloat16* s3, int k0, int t)
{
    const __nv_bfloat16* srcs[4] = {s0, s1, s2, s3};
    #pragma unroll
    for (int tl = 0; tl < 4; ++tl) {
        #pragma unroll
        for (int it = 0; it < 4; ++it) {
            int idx = t + it * 256;               // 0..1023
            int r = idx >> 3, c = idx & 7;
            cp16(smem_u32(tp + tl * TILE_ELEMS + r * TSTRIDE + c * 8),
                 srcs[tl] + (size_t)r * STRIDE + k0 + c * 8);
        }
    }
}

// ---------------------------------------------------------------------------
// Warp-MMA mainloop over one staged 64-chunk: 3 split passes (hh, lh, hl)
// acc[4][4][4]; warp tile 64x32 at (wm, wn) inside the 128x128 CTA tile
// ---------------------------------------------------------------------------
__device__ __forceinline__ void mma_chunk_warp(
    float acc[4][4][4], uint32_t bufOff,
    uint32_t aBaseH, uint32_t aBaseL, uint32_t bBaseH, uint32_t bBaseL)
{
    const uint32_t aH = aBaseH + bufOff, aL = aBaseL + bufOff;
    const uint32_t bH = bBaseH + bufOff, bL = bBaseL + bufOff;
    #pragma unroll
    for (int ks = 0; ks < 4; ++ks) {
        uint32_t bh[4][2], bl[4][2];
        #pragma unroll
        for (int nt = 0; nt < 4; ++nt) {
            ldm2(bh[nt], bH + nt * (8 * TSTRIDE * 2) + ks * 32);
            ldm2(bl[nt], bL + nt * (8 * TSTRIDE * 2) + ks * 32);
        }
        #pragma unroll
        for (int mt = 0; mt < 4; ++mt) {
            uint32_t ah[4], al[4];
            ldm4(ah, aH + mt * (16 * TSTRIDE * 2) + ks * 32);
            ldm4(al, aL + mt * (16 * TSTRIDE * 2) + ks * 32);
            #pragma unroll
            for (int nt = 0; nt < 4; ++nt) {
                mma16816(acc[mt][nt], ah, bh[nt]);
                mma16816(acc[mt][nt], al, bh[nt]);
                mma16816(acc[mt][nt], ah, bl[nt]);
            }
        }
    }
}

// Per-thread ldmatrix base addresses inside buffer 0
__device__ __forceinline__ void frag_bases(
    uint32_t sbase, int wm, int wn, int lane,
    uint32_t& aBaseH, uint32_t& aBaseL, uint32_t& bBaseH, uint32_t& bBaseL)
{
    const int lr = lane & 7;
    const int sel = lane >> 3;                   // 0..3
    const int aRow = wm + (sel & 1) * 8 + lr;
    const int aK   = (sel >> 1) * 8;
    aBaseH = sbase + 2u * (0 * TILE_ELEMS + aRow * TSTRIDE + aK);
    aBaseL = sbase + 2u * (1 * TILE_ELEMS + aRow * TSTRIDE + aK);
    const int bRow = wn + lr;
    const int bK   = (sel & 1) * 8;
    bBaseH = sbase + 2u * (2 * TILE_ELEMS + bRow * TSTRIDE + bK);
    bBaseL = sbase + 2u * (3 * TILE_ELEMS + bRow * TSTRIDE + bK);
}

// ---------------------------------------------------------------------------
// K3: QK^T upper-triangular tiles via warp HMMA, cp.async double-buffered
// ---------------------------------------------------------------------------
__global__ __launch_bounds__(256)
void qk_mma_kernel()
{
    extern __shared__ __nv_bfloat16 smem[];
    const uint32_t sbase = smem_u32(smem);
    const int t = threadIdx.x;
    const int lane = t & 31, wid = t >> 5;
    const int wm = (wid >> 2) * 64;     // warp m offset (0 or 64)
    const int wn = (wid & 3) * 32;      // warp n offset (0,32,64,96)

    int p = blockIdx.x, ti = 0;
    while (p >= NTILE - ti) { p -= NTILE - ti; ti++; }
    const int tj = ti + p;
    const int b  = blockIdx.y;
    const int m0 = ti * 128, n0 = tj * 128;

    const __nv_bfloat16* Ah = g_q_hi + ((size_t)b * SEQ + m0) * HEAD;
    const __nv_bfloat16* Al = g_q_lo + ((size_t)b * SEQ + m0) * HEAD;
    const __nv_bfloat16* Bh = g_k_hi + ((size_t)b * SEQ + n0) * HEAD;
    const __nv_bfloat16* Bl = g_k_lo + ((size_t)b * SEQ + n0) * HEAD;

    uint32_t aBH, aBL, bBH, bBL;
    frag_bases(sbase, wm, wn, lane, aBH, aBL, bBH, bBL);

    float acc[4][4][4];
    #pragma unroll
    for (int i = 0; i < 4; i++)
        #pragma unroll
        for (int j = 0; j < 4; j++)
            #pragma unroll
            for (int r = 0; r < 4; r++) acc[i][j][r] = 0.0f;

    const int nch = HEAD / 64;
    load_tiles_async<HEAD>(smem, Ah, Al, Bh, Bl, 0, t);
    CP_COMMIT();

    for (int c = 0; c < nch; ++c) {
        if (c + 1 < nch) {
            load_tiles_async<HEAD>(smem + ((c + 1) & 1) * BUF_ELEMS,
                                   Ah, Al, Bh, Bl, (c + 1) * 64, t);
            CP_COMMIT();
            cp_wait<1>();
        } else {
            cp_wait<0>();
        }
        __syncthreads();
        mma_chunk_warp(acc, (c & 1) * BUF_BYTES, aBH, aBL, bBH, bBL);
        __syncthreads();
    }

    // epilogue: scaled logits to g_p
    float* C = g_p + (size_t)b * SEQ * SEQ;
    const int row0 = m0 + wm + (lane >> 2);
    const int col0 = n0 + wn + (lane & 3) * 2;
    #pragma unroll
    for (int mt = 0; mt < 4; ++mt)
        #pragma unroll
        for (int nt = 0; nt < 4; ++nt) {
            int r1 = row0 + mt * 16, c1 = col0 + nt * 8;
            *(float2*)&C[(size_t)r1 * SEQ + c1] =
                make_float2(acc[mt][nt][0] * 0.25f, acc[mt][nt][1] * 0.25f);
            *(float2*)&C[(size_t)(r1 + 8) * SEQ + c1] =
                make_float2(acc[mt][nt][2] * 0.25f, acc[mt][nt][3] * 0.25f);
        }
}

// ---------------------------------------------------------------------------
// K4: row softmax (reference-faithful masking), writes P hi/lo bf16.
// Only the j >= (i & ~127) region is ever read downstream (PV starts at the
// row's tile); groups left of it are skipped for both load and store.
// ---------------------------------------------------------------------------
__global__ __launch_bounds__(256)
void softmax_kernel()
{
    const size_t row = blockIdx.x;
    const int i = (int)(row & (SEQ - 1));
    const int j0 = i & ~127;              // row-tile start; multiple of 128
    const float* r = g_p + row * SEQ;
    __nv_bfloat16* ph = g_p_hi + row * SEQ;
    __nv_bfloat16* pl = g_p_lo + row * SEQ;
    const int t = threadIdx.x;

    const int g0 = t * 4, g1 = 1024 + t * 4;   // float4 groups (4-aligned)
    const bool act0 = g0 >= j0;
    const bool act1 = g1 >= j0;

    float l[8];
    if (act0) {
        float4 v0 = *(const float4*)&r[g0];
        l[0] = v0.x; l[1] = v0.y; l[2] = v0.z; l[3] = v0.w;
    } else { l[0] = l[1] = l[2] = l[3] = -9.0e15f; }
    if (act1) {
        float4 v1 = *(const float4*)&r[g1];
        l[4] = v1.x; l[5] = v1.y; l[6] = v1.z; l[7] = v1.w;
    } else { l[4] = l[5] = l[6] = l[7] = -9.0e15f; }

    float m = -3.0e38f;
    #pragma unroll
    for (int e = 0; e < 8; e++) {
        int j = (e < 4) ? (g0 + e) : (g1 + (e - 4));
        l[e] = (j >= i && l[e] != 0.0f) ? l[e] : -9.0e15f;
        m = fmaxf(m, l[e]);
    }

    __shared__ float smax[8];
    __shared__ float ssum[8];

    #pragma unroll
    for (int o = 16; o; o >>= 1) m = fmaxf(m, __shfl_xor_sync(0xffffffffu, m, o));
    if ((t & 31) == 0) smax[t >> 5] = m;
    __syncthreads();
    if (t == 0) {
        float x = smax[0];
        #pragma unroll
        for (int w = 1; w < 8; w++) x = fmaxf(x, smax[w]);
        smax[0] = x;
    }
    __syncthreads();
    const float bm = smax[0];

    float s = 0.0f;
    float pb[8];
    #pragma unroll
    for (int e = 0; e < 8; e++) { pb[e] = __expf(l[e] - bm); s += pb[e]; }
    #pragma unroll
    for (int o = 16; o; o >>= 1) s += __shfl_xor_sync(0xffffffffu, s, o);
    if ((t & 31) == 0) ssum[t >> 5] = s;
    __syncthreads();
    if (t == 0) {
        float x = ssum[0];
        #pragma unroll
        for (int w = 1; w < 8; w++) x += ssum[w];
        ssum[0] = x;
    }
    __syncthreads();
    const float inv = 1.0f / ssum[0];

    #pragma unroll
    for (int h = 0; h < 2; h++) {
        if (!(h == 0 ? act0 : act1)) continue;
        int col = (h == 0) ? g0 : g1;
        __nv_bfloat16 h0, l0, h1, l1, h2, l2, h3, l3;
        split_bf16(pb[h * 4 + 0] * inv, h0, l0);
        split_bf16(pb[h * 4 + 1] * inv, h1, l1);
        split_bf16(pb[h * 4 + 2] * inv, h2, l2);
        split_bf16(pb[h * 4 + 3] * inv, h3, l3);
        ushort4 hs, ls;
        hs.x = __bfloat16_as_ushort(h0); hs.y = __bfloat16_as_ushort(h1);
        hs.z = __bfloat16_as_ushort(h2); hs.w = __bfloat16_as_ushort(h3);
        ls.x = __bfloat16_as_ushort(l0); ls.y = __bfloat16_as_ushort(l1);
        ls.z = __bfloat16_as_ushort(l2); ls.w = __bfloat16_as_ushort(l3);
        *(ushort4*)&ph[col] = hs;
        *(ushort4*)&pl[col] = ls;
    }
}

// ---------------------------------------------------------------------------
// K5: out = P @ V via warp HMMA, cp.async double-buffered, triangular K skip
// ---------------------------------------------------------------------------
__global__ __launch_bounds__(256)
void pv_mma_kernel(float* __restrict__ Out)
{
    extern __shared__ __nv_bfloat16 smem[];
    const uint32_t sbase = smem_u32(smem);
    const int t = threadIdx.x;
    const int lane = t & 31, wid = t >> 5;
    const int wm = (wid >> 2) * 64;
    const int wn = (wid & 3) * 32;

    const int b  = blockIdx.z;
    const int ti = blockIdx.y;
    const int n0 = blockIdx.x * 128;
    const int m0 = ti * 128;

    const __nv_bfloat16* Ah = g_p_hi  + ((size_t)b * SEQ + m0) * SEQ;
    const __nv_bfloat16* Al = g_p_lo  + ((size_t)b * SEQ + m0) * SEQ;
    const __nv_bfloat16* Bh = g_vt_hi + ((size_t)b * HEAD + n0) * SEQ;
    const __nv_bfloat16* Bl = g_vt_lo + ((size_t)b * HEAD + n0) * SEQ;

    uint32_t aBH, aBL, bBH, bBL;
    frag_bases(sbase, wm, wn, lane, aBH, aBL, bBH, bBL);

    float acc[4][4][4];
    #pragma unroll
    for (int i = 0; i < 4; i++)
        #pragma unroll
        for (int j = 0; j < 4; j++)
            #pragma unroll
            for (int r = 0; r < 4; r++) acc[i][j][r] = 0.0f;

    const int nch = (SEQ - m0) / 64;
    load_tiles_async<SEQ>(smem, Ah, Al, Bh, Bl, m0, t);
    CP_COMMIT();

    for (int c = 0; c < nch; ++c) {
        if (c + 1 < nch) {
            load_tiles_async<SEQ>(smem + ((c + 1) & 1) * BUF_ELEMS,
                                  Ah, Al, Bh, Bl, m0 + (c + 1) * 64, t);
            CP_COMMIT();
            cp_wait<1>();
        } else {
            cp_wait<0>();
        }
        __syncthreads();
        mma_chunk_warp(acc, (c & 1) * BUF_BYTES, aBH, aBL, bBH, bBL);
        __syncthreads();
    }

    float* C = Out + (size_t)b * SEQ * HEAD;
    const int row0 = m0 + wm + (lane >> 2);
    const int col0 = n0 + wn + (lane & 3) * 2;
    #pragma unroll
    for (int mt = 0; mt < 4; ++mt)
        #pragma unroll
        for (int nt = 0; nt < 4; ++nt) {
            int r1 = row0 + mt * 16, c1 = col0 + nt * 8;
            *(float2*)&C[(size_t)r1 * HEAD + c1] =
                make_float2(acc[mt][nt][0], acc[mt][nt][1]);
            *(float2*)&C[(size_t)(r1 + 8) * HEAD + c1] =
                make_float2(acc[mt][nt][2], acc[mt][nt][3]);
        }
}

// ---------------------------------------------------------------------------
extern "C" void kernel_launch(void* const* d_in, const int* in_sizes, int n_in,
                              void* d_out, int out_size)
{
    (void)in_sizes; (void)n_in; (void)out_size;
    const float* x = (const float*)d_in[0];   // [16, 2048, 64]
    const float* W = (const float*)d_in[1];   // [64, 3072]
    float* out = (float*)d_out;               // [16, 2048, 1024]

    cudaFuncSetAttribute(qk_mma_kernel, cudaFuncAttributeMaxDynamicSharedMemorySize, SMEM_BYTES);
    cudaFuncSetAttribute(pv_mma_kernel, cudaFuncAttributeMaxDynamicSharedMemorySize, SMEM_BYTES);

    qkv_kernel<<<dim3(QKVW / 128, (BATCH * SEQ) / 128), 256>>>(x, W);
    vt_kernel<<<dim3(HEAD / 64, SEQ / 64, BATCH), 256>>>();
    qk_mma_kernel<<<dim3(NTILE * (NTILE + 1) / 2, BATCH), 256, SMEM_BYTES>>>();
    softmax_kernel<<<dim3(BATCH * SEQ), 256>>>();
    pv_mma_kernel<<<dim3(HEAD / 128, NTILE, BATCH), 256, SMEM_BYTES>>>(out);
}

// round 17
// speedup vs baseline: 2.2529x; 1.0058x over previous
#include <cuda_runtime.h>
#include <cuda_bf16.h>
#include <cstdint>

// Problem constants
#define BATCH 16
#define SEQ   2048
#define DMODEL 64
#define HEAD  1024
#define QKVW  3072
#define NTILE 16      // SEQ/128

// Padded smem tile geometry (bf16): 128 rows x 64 cols, stride 72 (conflict-free LDSM)
#define TSTRIDE 72
#define TILE_ELEMS (128 * TSTRIDE)            // 9216 bf16 per tile
#define BUF_ELEMS  (4 * TILE_ELEMS)           // Ah, Al, Bh, Bl
#define BUF_BYTES  (BUF_ELEMS * 2)            // 73728 B
#define SMEM_BYTES (2 * BUF_BYTES)            // double buffered = 147456 B

// ---------------------------------------------------------------------------
// Scratch (device globals; allocations are forbidden)
// ---------------------------------------------------------------------------
__device__ __align__(16) __nv_bfloat16 g_q_hi[(size_t)BATCH * SEQ * HEAD];
__device__ __align__(16) __nv_bfloat16 g_q_lo[(size_t)BATCH * SEQ * HEAD];
__device__ __align__(16) __nv_bfloat16 g_k_hi[(size_t)BATCH * SEQ * HEAD];
__device__ __align__(16) __nv_bfloat16 g_k_lo[(size_t)BATCH * SEQ * HEAD];
__device__ __align__(16) float         g_v   [(size_t)BATCH * SEQ * HEAD];
__device__ __align__(16) __nv_bfloat16 g_vt_hi[(size_t)BATCH * HEAD * SEQ];
__device__ __align__(16) __nv_bfloat16 g_vt_lo[(size_t)BATCH * HEAD * SEQ];
__device__ __align__(16) float         g_p   [(size_t)BATCH * SEQ * SEQ];
__device__ __align__(16) __nv_bfloat16 g_p_hi[(size_t)BATCH * SEQ * SEQ];
__device__ __align__(16) __nv_bfloat16 g_p_lo[(size_t)BATCH * SEQ * SEQ];

// ---------------------------------------------------------------------------
// Warp-MMA + cp.async primitives (sm_80-compatible PTX under compute_103)
// ---------------------------------------------------------------------------
__device__ __forceinline__ uint32_t smem_u32(const void* p) {
    uint32_t a;
    asm("{ .reg .u64 t; cvta.to.shared.u64 t, %1; cvt.u32.u64 %0, t; }"
        : "=r"(a) : "l"(p));
    return a;
}
__device__ __forceinline__ void ldm4(uint32_t* r, uint32_t a) {
    asm volatile("ldmatrix.sync.aligned.m8n8.x4.shared.b16 {%0,%1,%2,%3}, [%4];"
                 : "=r"(r[0]), "=r"(r[1]), "=r"(r[2]), "=r"(r[3]) : "r"(a));
}
__device__ __forceinline__ void mma16816(float* c, const uint32_t* a, const uint32_t* b) {
    asm volatile(
        "mma.sync.aligned.m16n8k16.row.col.f32.bf16.bf16.f32 "
        "{%0,%1,%2,%3}, {%4,%5,%6,%7}, {%8,%9}, {%0,%1,%2,%3};"
        : "+f"(c[0]), "+f"(c[1]), "+f"(c[2]), "+f"(c[3])
        : "r"(a[0]), "r"(a[1]), "r"(a[2]), "r"(a[3]), "r"(b[0]), "r"(b[1]));
}
__device__ __forceinline__ void cp16(uint32_t dst, const void* src) {
    asm volatile("cp.async.cg.shared.global [%0], [%1], 16;"
                 :: "r"(dst), "l"(src));
}
#define CP_COMMIT() asm volatile("cp.async.commit_group;" ::: "memory")
template <int N>
__device__ __forceinline__ void cp_wait() {
    asm volatile("cp.async.wait_group %0;" :: "n"(N) : "memory");
}

// bf16 split helpers
__device__ __forceinline__ void split_bf16(float x, __nv_bfloat16& h, __nv_bfloat16& l) {
    h = __float2bfloat16_rn(x);
    l = __float2bfloat16_rn(x - __bfloat162float(h));
}

// ---------------------------------------------------------------------------
// K1: QKV projection (fp32 SIMT), epilogue emits q/k hi+lo bf16 and v fp32
// ---------------------------------------------------------------------------
__global__ __launch_bounds__(256)
void qkv_kernel(const float* __restrict__ X, const float* __restrict__ W)
{
    __shared__ float As[8][128];
    __shared__ float Bs[8][128];

    const int m0 = blockIdx.y * 128;
    const int n0 = blockIdx.x * 128;
    const int t  = threadIdx.x;
    const int tx = t & 15, ty = t >> 4;
    const int arow = t >> 1, acol = (t & 1) * 4;
    const int bk = t >> 5,  bn = (t & 31) * 4;

    float acc[8][8];
    #pragma unroll
    for (int i = 0; i < 8; i++)
        #pragma unroll
        for (int j = 0; j < 8; j++) acc[i][j] = 0.0f;

    for (int k0 = 0; k0 < DMODEL; k0 += 8) {
        float4 av = *(const float4*)&X[(size_t)(m0 + arow) * DMODEL + k0 + acol];
        As[acol + 0][arow] = av.x; As[acol + 1][arow] = av.y;
        As[acol + 2][arow] = av.z; As[acol + 3][arow] = av.w;
        *(float4*)&Bs[bk][bn] = *(const float4*)&W[(size_t)(k0 + bk) * QKVW + n0 + bn];
        __syncthreads();
        #pragma unroll
        for (int kc = 0; kc < 8; ++kc) {
            float4 a0 = *(const float4*)&As[kc][ty * 4];
            float4 a1 = *(const float4*)&As[kc][64 + ty * 4];
            float4 b0 = *(const float4*)&Bs[kc][tx * 4];
            float4 b1 = *(const float4*)&Bs[kc][64 + tx * 4];
            float a[8] = {a0.x, a0.y, a0.z, a0.w, a1.x, a1.y, a1.z, a1.w};
            float b[8] = {b0.x, b0.y, b0.z, b0.w, b1.x, b1.y, b1.z, b1.w};
            #pragma unroll
            for (int i = 0; i < 8; i++)
                #pragma unroll
                for (int j = 0; j < 8; j++)
                    acc[i][j] += a[i] * b[j];
        }
        __syncthreads();
    }

    const int sec = n0 >> 10;              // 0=q, 1=k, 2=v
    const int cb  = n0 & 1023;

    #pragma unroll
    for (int i = 0; i < 8; i++) {
        int row = m0 + ((i < 4) ? (ty * 4 + i) : (64 + ty * 4 + (i - 4)));
        #pragma unroll
        for (int h = 0; h < 2; h++) {
            int col = cb + h * 64 + tx * 4;
            float v0 = acc[i][h * 4 + 0], v1 = acc[i][h * 4 + 1];
            float v2 = acc[i][h * 4 + 2], v3 = acc[i][h * 4 + 3];
            if (sec == 2) {
                *(float4*)&g_v[(size_t)row * HEAD + col] = make_float4(v0, v1, v2, v3);
            } else {
                __nv_bfloat16 h0, l0, h1, l1, h2, l2, h3, l3;
                split_bf16(v0, h0, l0); split_bf16(v1, h1, l1);
                split_bf16(v2, h2, l2); split_bf16(v3, h3, l3);
                __nv_bfloat16* hp = sec == 0 ? g_q_hi : g_k_hi;
                __nv_bfloat16* lp = sec == 0 ? g_q_lo : g_k_lo;
                ushort4 hs, ls;
                hs.x = __bfloat16_as_ushort(h0); hs.y = __bfloat16_as_ushort(h1);
                hs.z = __bfloat16_as_ushort(h2); hs.w = __bfloat16_as_ushort(h3);
                ls.x = __bfloat16_as_ushort(l0); ls.y = __bfloat16_as_ushort(l1);
                ls.z = __bfloat16_as_ushort(l2); ls.w = __bfloat16_as_ushort(l3);
                *(ushort4*)&hp[(size_t)row * HEAD + col] = hs;
                *(ushort4*)&lp[(size_t)row * HEAD + col] = ls;
            }
        }
    }
}

// ---------------------------------------------------------------------------
// K2: transpose v (fp32) -> vt hi/lo (bf16), per-batch [HEAD][SEQ]
// ---------------------------------------------------------------------------
__global__ __launch_bounds__(256)
void vt_kernel()
{
    __shared__ float tile[64][65];
    const int b  = blockIdx.z;
    const int s0 = blockIdx.y * 64;
    const int n0 = blockIdx.x * 64;
    const float* V = g_v + (size_t)b * SEQ * HEAD;
    const int t = threadIdx.x;

    #pragma unroll
    for (int i = 0; i < 16; i++) {
        int idx = t + i * 256;
        int r = idx >> 6, c = idx & 63;
        tile[r][c] = V[(size_t)(s0 + r) * HEAD + n0 + c];
    }
    __syncthreads();
    #pragma unroll
    for (int i = 0; i < 16; i++) {
        int idx = t + i * 256;
        int r = idx >> 6, c = idx & 63;       // r = local n, c = local s
        float x = tile[c][r];
        __nv_bfloat16 h, l;
        split_bf16(x, h, l);
        size_t o = ((size_t)b * HEAD + n0 + r) * SEQ + s0 + c;
        g_vt_hi[o] = h;
        g_vt_lo[o] = l;
    }
}

// ---------------------------------------------------------------------------
// Async tile loader: 4 tiles of [128 rows x 64 bf16] into padded smem buffer
// ---------------------------------------------------------------------------
template <int STRIDE>
__device__ __forceinline__ void load_tiles_async(__nv_bfloat16* tp,
    const __nv_bfloat16* s0, const __nv_bfloat16* s1,
    const __nv_bfloat16* s2, const __nv_bfloat16* s3, int k0, int t)
{
    const __nv_bfloat16* srcs[4] = {s0, s1, s2, s3};
    #pragma unroll
    for (int tl = 0; tl < 4; ++tl) {
        #pragma unroll
        for (int it = 0; it < 4; ++it) {
            int idx = t + it * 256;               // 0..1023
            int r = idx >> 3, c = idx & 7;
            cp16(smem_u32(tp + tl * TILE_ELEMS + r * TSTRIDE + c * 8),
                 srcs[tl] + (size_t)r * STRIDE + k0 + c * 8);
        }
    }
}

// ---------------------------------------------------------------------------
// Warp-MMA mainloop over one staged 64-chunk: pass-major (hh, lh, hl) so each
// accumulator's dependent MMAs are spaced by 15 independent ones.
// acc[4][4][4]; warp tile 64x32 at (wm, wn) inside the 128x128 CTA tile
// ---------------------------------------------------------------------------
__device__ __forceinline__ void mma_chunk_warp(
    float acc[4][4][4], uint32_t bufOff,
    uint32_t aBaseH, uint32_t aBaseL, uint32_t bBaseH, uint32_t bBaseL)
{
    const uint32_t aH = aBaseH + bufOff, aL = aBaseL + bufOff;
    const uint32_t bH = bBaseH + bufOff, bL = bBaseL + bufOff;
    #pragma unroll
    for (int ks = 0; ks < 4; ++ks) {
        // Front-batch ALL fragment loads for this k16 step
        uint32_t ah[4][4], al[4][4];
        #pragma unroll
        for (int mt = 0; mt < 4; ++mt) {
            ldm4(ah[mt], aH + mt * (16 * TSTRIDE * 2) + ks * 32);
            ldm4(al[mt], aL + mt * (16 * TSTRIDE * 2) + ks * 32);
        }
        uint32_t bh[4][2], bl[4][2];
        #pragma unroll
        for (int pr = 0; pr < 2; ++pr) {
            uint32_t r[4];
            ldm4(r, bH + pr * (16 * TSTRIDE * 2) + ks * 32);
            bh[2 * pr][0] = r[0]; bh[2 * pr][1] = r[1];
            bh[2 * pr + 1][0] = r[2]; bh[2 * pr + 1][1] = r[3];
            ldm4(r, bL + pr * (16 * TSTRIDE * 2) + ks * 32);
            bl[2 * pr][0] = r[0]; bl[2 * pr][1] = r[1];
            bl[2 * pr + 1][0] = r[2]; bl[2 * pr + 1][1] = r[3];
        }
        // Pass-major issue: 16 independent MMAs between dependent reuses
        #pragma unroll
        for (int mt = 0; mt < 4; ++mt)
            #pragma unroll
            for (int nt = 0; nt < 4; ++nt)
                mma16816(acc[mt][nt], ah[mt], bh[nt]);
        #pragma unroll
        for (int mt = 0; mt < 4; ++mt)
            #pragma unroll
            for (int nt = 0; nt < 4; ++nt)
                mma16816(acc[mt][nt], al[mt], bh[nt]);
        #pragma unroll
        for (int mt = 0; mt < 4; ++mt)
            #pragma unroll
            for (int nt = 0; nt < 4; ++nt)
                mma16816(acc[mt][nt], ah[mt], bl[nt]);
    }
}

// Per-thread ldmatrix base addresses inside buffer 0.
// A x4: mats (m0,k0),(m8,k0),(m0,k8),(m8,k8). B x4: mats (n0,k0),(n0,k8),(n8,k0),(n8,k8).
__device__ __forceinline__ void frag_bases(
    uint32_t sbase, int wm, int wn, int lane,
    uint32_t& aBaseH, uint32_t& aBaseL, uint32_t& bBaseH, uint32_t& bBaseL)
{
    const int lr = lane & 7;
    const int sel = lane >> 3;                   // 0..3
    const int aRow = wm + (sel & 1) * 8 + lr;
    const int aK   = (sel >> 1) * 8;
    aBaseH = sbase + 2u * (0 * TILE_ELEMS + aRow * TSTRIDE + aK);
    aBaseL = sbase + 2u * (1 * TILE_ELEMS + aRow * TSTRIDE + aK);
    const int bRow = wn + (sel >> 1) * 8 + lr;
    const int bK   = (sel & 1) * 8;
    bBaseH = sbase + 2u * (2 * TILE_ELEMS + bRow * TSTRIDE + bK);
    bBaseL = sbase + 2u * (3 * TILE_ELEMS + bRow * TSTRIDE + bK);
}

// ---------------------------------------------------------------------------
// K3: QK^T upper-triangular tiles via warp HMMA, cp.async double-buffered
// ---------------------------------------------------------------------------
__global__ __launch_bounds__(256)
void qk_mma_kernel()
{
    extern __shared__ __nv_bfloat16 smem[];
    const uint32_t sbase = smem_u32(smem);
    const int t = threadIdx.x;
    const int lane = t & 31, wid = t >> 5;
    const int wm = (wid >> 2) * 64;     // warp m offset (0 or 64)
    const int wn = (wid & 3) * 32;      // warp n offset (0,32,64,96)

    int p = blockIdx.x, ti = 0;
    while (p >= NTILE - ti) { p -= NTILE - ti; ti++; }
    const int tj = ti + p;
    const int b  = blockIdx.y;
    const int m0 = ti * 128, n0 = tj * 128;

    const __nv_bfloat16* Ah = g_q_hi + ((size_t)b * SEQ + m0) * HEAD;
    const __nv_bfloat16* Al = g_q_lo + ((size_t)b * SEQ + m0) * HEAD;
    const __nv_bfloat16* Bh = g_k_hi + ((size_t)b * SEQ + n0) * HEAD;
    const __nv_bfloat16* Bl = g_k_lo + ((size_t)b * SEQ + n0) * HEAD;

    uint32_t aBH, aBL, bBH, bBL;
    frag_bases(sbase, wm, wn, lane, aBH, aBL, bBH, bBL);

    float acc[4][4][4];
    #pragma unroll
    for (int i = 0; i < 4; i++)
        #pragma unroll
        for (int j = 0; j < 4; j++)
            #pragma unroll
            for (int r = 0; r < 4; r++) acc[i][j][r] = 0.0f;

    const int nch = HEAD / 64;
    load_tiles_async<HEAD>(smem, Ah, Al, Bh, Bl, 0, t);
    CP_COMMIT();

    for (int c = 0; c < nch; ++c) {
        if (c + 1 < nch) {
            load_tiles_async<HEAD>(smem + ((c + 1) & 1) * BUF_ELEMS,
                                   Ah, Al, Bh, Bl, (c + 1) * 64, t);
            CP_COMMIT();
            cp_wait<1>();
        } else {
            cp_wait<0>();
        }
        __syncthreads();
        mma_chunk_warp(acc, (c & 1) * BUF_BYTES, aBH, aBL, bBH, bBL);
        __syncthreads();
    }

    // epilogue: scaled logits to g_p
    float* C = g_p + (size_t)b * SEQ * SEQ;
    const int row0 = m0 + wm + (lane >> 2);
    const int col0 = n0 + wn + (lane & 3) * 2;
    #pragma unroll
    for (int mt = 0; mt < 4; ++mt)
        #pragma unroll
        for (int nt = 0; nt < 4; ++nt) {
            int r1 = row0 + mt * 16, c1 = col0 + nt * 8;
            *(float2*)&C[(size_t)r1 * SEQ + c1] =
                make_float2(acc[mt][nt][0] * 0.25f, acc[mt][nt][1] * 0.25f);
            *(float2*)&C[(size_t)(r1 + 8) * SEQ + c1] =
                make_float2(acc[mt][nt][2] * 0.25f, acc[mt][nt][3] * 0.25f);
        }
}

// ---------------------------------------------------------------------------
// K4: row softmax (reference-faithful masking), writes P hi/lo bf16.
// Only the j >= (i & ~127) region is ever read downstream (PV starts at the
// row's tile); groups left of it are skipped for both load and store.
// ---------------------------------------------------------------------------
__global__ __launch_bounds__(256)
void softmax_kernel()
{
    const size_t row = blockIdx.x;
    const int i = (int)(row & (SEQ - 1));
    const int j0 = i & ~127;              // row-tile start; multiple of 128
    const float* r = g_p + row * SEQ;
    __nv_bfloat16* ph = g_p_hi + row * SEQ;
    __nv_bfloat16* pl = g_p_lo + row * SEQ;
    const int t = threadIdx.x;

    const int g0 = t * 4, g1 = 1024 + t * 4;   // float4 groups (4-aligned)
    const bool act0 = g0 >= j0;
    const bool act1 = g1 >= j0;

    float l[8];
    if (act0) {
        float4 v0 = *(const float4*)&r[g0];
        l[0] = v0.x; l[1] = v0.y; l[2] = v0.z; l[3] = v0.w;
    } else { l[0] = l[1] = l[2] = l[3] = -9.0e15f; }
    if (act1) {
        float4 v1 = *(const float4*)&r[g1];
        l[4] = v1.x; l[5] = v1.y; l[6] = v1.z; l[7] = v1.w;
    } else { l[4] = l[5] = l[6] = l[7] = -9.0e15f; }

    float m = -3.0e38f;
    #pragma unroll
    for (int e = 0; e < 8; e++) {
        int j = (e < 4) ? (g0 + e) : (g1 + (e - 4));
        l[e] = (j >= i && l[e] != 0.0f) ? l[e] : -9.0e15f;
        m = fmaxf(m, l[e]);
    }

    __shared__ float smax[8];
    __shared__ float ssum[8];

    #pragma unroll
    for (int o = 16; o; o >>= 1) m = fmaxf(m, __shfl_xor_sync(0xffffffffu, m, o));
    if ((t & 31) == 0) smax[t >> 5] = m;
    __syncthreads();
    if (t == 0) {
        float x = smax[0];
        #pragma unroll
        for (int w = 1; w < 8; w++) x = fmaxf(x, smax[w]);
        smax[0] = x;
    }
    __syncthreads();
    const float bm = smax[0];

    float s = 0.0f;
    float pb[8];
    #pragma unroll
    for (int e = 0; e < 8; e++) { pb[e] = __expf(l[e] - bm); s += pb[e]; }
    #pragma unroll
    for (int o = 16; o; o >>= 1) s += __shfl_xor_sync(0xffffffffu, s, o);
    if ((t & 31) == 0) ssum[t >> 5] = s;
    __syncthreads();
    if (t == 0) {
        float x = ssum[0];
        #pragma unroll
        for (int w = 1; w < 8; w++) x += ssum[w];
        ssum[0] = x;
    }
    __syncthreads();
    const float inv = 1.0f / ssum[0];

    #pragma unroll
    for (int h = 0; h < 2; h++) {
        if (!(h == 0 ? act0 : act1)) continue;
        int col = (h == 0) ? g0 : g1;
        __nv_bfloat16 h0, l0, h1, l1, h2, l2, h3, l3;
        split_bf16(pb[h * 4 + 0] * inv, h0, l0);
        split_bf16(pb[h * 4 + 1] * inv, h1, l1);
        split_bf16(pb[h * 4 + 2] * inv, h2, l2);
        split_bf16(pb[h * 4 + 3] * inv, h3, l3);
        ushort4 hs, ls;
        hs.x = __bfloat16_as_ushort(h0); hs.y = __bfloat16_as_ushort(h1);
        hs.z = __bfloat16_as_ushort(h2); hs.w = __bfloat16_as_ushort(h3);
        ls.x = __bfloat16_as_ushort(l0); ls.y = __bfloat16_as_ushort(l1);
        ls.z = __bfloat16_as_ushort(l2); ls.w = __bfloat16_as_ushort(l3);
        *(ushort4*)&ph[col] = hs;
        *(ushort4*)&pl[col] = ls;
    }
}

// ---------------------------------------------------------------------------
// K5: out = P @ V via warp HMMA, cp.async double-buffered, triangular K skip
// ---------------------------------------------------------------------------
__global__ __launch_bounds__(256)
void pv_mma_kernel(float* __restrict__ Out)
{
    extern __shared__ __nv_bfloat16 smem[];
    const uint32_t sbase = smem_u32(smem);
    const int t = threadIdx.x;
    const int lane = t & 31, wid = t >> 5;
    const int wm = (wid >> 2) * 64;
    const int wn = (wid & 3) * 32;

    const int b  = blockIdx.z;
    const int ti = blockIdx.y;
    const int n0 = blockIdx.x * 128;
    const int m0 = ti * 128;

    const __nv_bfloat16* Ah = g_p_hi  + ((size_t)b * SEQ + m0) * SEQ;
    const __nv_bfloat16* Al = g_p_lo  + ((size_t)b * SEQ + m0) * SEQ;
    const __nv_bfloat16* Bh = g_vt_hi + ((size_t)b * HEAD + n0) * SEQ;
    const __nv_bfloat16* Bl = g_vt_lo + ((size_t)b * HEAD + n0) * SEQ;

    uint32_t aBH, aBL, bBH, bBL;
    frag_bases(sbase, wm, wn, lane, aBH, aBL, bBH, bBL);

    float acc[4][4][4];
    #pragma unroll
    for (int i = 0; i < 4; i++)
        #pragma unroll
        for (int j = 0; j < 4; j++)
            #pragma unroll
            for (int r = 0; r < 4; r++) acc[i][j][r] = 0.0f;

    const int nch = (SEQ - m0) / 64;
    load_tiles_async<SEQ>(smem, Ah, Al, Bh, Bl, m0, t);
    CP_COMMIT();

    for (int c = 0; c < nch; ++c) {
        if (c + 1 < nch) {
            load_tiles_async<SEQ>(smem + ((c + 1) & 1) * BUF_ELEMS,
                                  Ah, Al, Bh, Bl, m0 + (c + 1) * 64, t);
            CP_COMMIT();
            cp_wait<1>();
        } else {
            cp_wait<0>();
        }
        __syncthreads();
        mma_chunk_warp(acc, (c & 1) * BUF_BYTES, aBH, aBL, bBH, bBL);
        __syncthreads();
    }

    float* C = Out + (size_t)b * SEQ * HEAD;
    const int row0 = m0 + wm + (lane >> 2);
    const int col0 = n0 + wn + (lane & 3) * 2;
    #pragma unroll
    for (int mt = 0; mt < 4; ++mt)
        #pragma unroll
        for (int nt = 0; nt < 4; ++nt) {
            int r1 = row0 + mt * 16, c1 = col0 + nt * 8;
            *(float2*)&C[(size_t)r1 * HEAD + c1] =
                make_float2(acc[mt][nt][0], acc[mt][nt][1]);
            *(float2*)&C[(size_t)(r1 + 8) * HEAD + c1] =
                make_float2(acc[mt][nt][2], acc[mt][nt][3]);
        }
}

// ---------------------------------------------------------------------------
extern "C" void kernel_launch(void* const* d_in, const int* in_sizes, int n_in,
                              void* d_out, int out_size)
{
    (void)in_sizes; (void)n_in; (void)out_size;
    const float* x = (const float*)d_in[0];   // [16, 2048, 64]
    const float* W = (const float*)d_in[1];   // [64, 3072]
    float* out = (float*)d_out;               // [16, 2048, 1024]

    cudaFuncSetAttribute(qk_mma_kernel, cudaFuncAttributeMaxDynamicSharedMemorySize, SMEM_BYTES);
    cudaFuncSetAttribute(pv_mma_kernel, cudaFuncAttributeMaxDynamicSharedMemorySize, SMEM_BYTES);

    qkv_kernel<<<dim3(QKVW / 128, (BATCH * SEQ) / 128), 256>>>(x, W);
    vt_kernel<<<dim3(HEAD / 64, SEQ / 64, BATCH), 256>>>();
    qk_mma_kernel<<<dim3(NTILE * (NTILE + 1) / 2, BATCH), 256, SMEM_BYTES>>>();
    softmax_kernel<<<dim3(BATCH * SEQ), 256>>>();
    pv_mma_kernel<<<dim3(HEAD / 128, NTILE, BATCH), 256, SMEM_BYTES>>>(out);
}